// round 6
// baseline (speedup 1.0000x reference)
#include <cuda_runtime.h>
#include <cuda_bf16.h>
#include <cstdint>

#define BB 1024
#define SS 512
#define TT 48
#define FULL 0xFFFFFFFFu
#define RING 16
#define LEAD (RING - 2)   // 14 steps of prefetch lead

typedef unsigned long long ull;

__device__ double g_scratch[BB];
__device__ unsigned int g_count = 0;
__device__ int g_len[BB];
__device__ int g_perm[BB];

__device__ __forceinline__ ull pack2f(float a, float b) {
    ull r;
    asm("mov.b64 %0, {%1, %2};" : "=l"(r) : "f"(a), "f"(b));
    return r;
}
__device__ __forceinline__ void unpack2f(ull v, float& lo, float& hi) {
    asm("mov.b64 {%0, %1}, %2;" : "=f"(lo), "=f"(hi) : "l"(v));
}
__device__ __forceinline__ void fma2(ull& acc, ull a, ull b) {
    asm("fma.rn.f32x2 %0, %1, %2, %0;" : "+l"(acc) : "l"(a), "l"(b));
}
__device__ __forceinline__ ull add2(ull a, ull b) {
    ull r;
    asm("add.rn.f32x2 %0, %1, %2;" : "=l"(r) : "l"(a), "l"(b));
    return r;
}
__device__ __forceinline__ float hsum2(ull a, ull b) {
    ull u = add2(a, b);
    float lo, hi;
    unpack2f(u, lo, hi);
    return lo + hi;
}
__device__ __forceinline__ float warp_sum_f(float v) {
    #pragma unroll
    for (int o = 16; o; o >>= 1) v += __shfl_xor_sync(FULL, v, o);
    return v;
}
// Predicated cp.async: no BSSY/BSYNC divergence cost.
__device__ __forceinline__ void cp_async16_pred(unsigned dst, const float* src, int go) {
    asm volatile(
        "{\n\t.reg .pred p;\n\t"
        "setp.ne.b32 p, %0, 0;\n\t"
        "@p cp.async.cg.shared.global [%1], [%2], 16;\n\t}"
        :: "r"(go), "r"(dst), "l"(src));
}

// ---------- pre-pass 1: sequence lengths ----------
extern "C" __global__ void __launch_bounds__(128)
len_kernel(const float* __restrict__ mask) {
    const int lane = threadIdx.x & 31;
    const int b = blockIdx.x * 4 + (threadIdx.x >> 5);
    float s = 0.f;
    #pragma unroll
    for (int k = 0; k < SS / 32; k++) s += mask[b * SS + k * 32 + lane];
    s = warp_sum_f(s);
    if (lane == 0) g_len[b] = __float2int_rn(s);
}

// ---------- pre-pass 2: counting sort of batches by length ----------
extern "C" __global__ void __launch_bounds__(512)
sort_kernel() {
    __shared__ int hist[SS + 1];
    const int tid = threadIdx.x;
    for (int i = tid; i <= SS; i += 512) hist[i] = 0;
    __syncthreads();
    for (int b = tid; b < BB; b += 512) atomicAdd(&hist[g_len[b]], 1);
    __syncthreads();
    if (tid == 0) {
        int acc = 0;
        for (int i = 0; i <= SS; i++) { int c = hist[i]; hist[i] = acc; acc += c; }
    }
    __syncthreads();
    for (int b = tid; b < BB; b += 512) {
        int r = atomicAdd(&hist[g_len[b]], 1);
        g_perm[r] = b;
    }
}

// One step of the product-domain recurrence for one batch.
// Reads partials from parity (t-1)&1 of pbufb_, writes parity t&1.
#define STEP_BODY(pA_, pB_, pC_, M_, ringb_, pbufb_) do {                          \
    const unsigned rb_ = (pbufb_) + (unsigned)(((t - 1) & 1) * 640);               \
    const unsigned wb_ = (pbufb_) + (unsigned)((t & 1) * 640);                     \
    const unsigned ea_ = (ringb_) + (unsigned)((t & (RING - 1)) * 192);            \
    float e0_, e1_, e2_;                                                           \
    asm volatile("ld.shared.f32 %0, [%1];" : "=f"(e0_) : "r"(ea_ + cA4));          \
    asm volatile("ld.shared.f32 %0, [%1];" : "=f"(e1_) : "r"(ea_ + cB4));          \
    asm volatile("ld.shared.f32 %0, [%1];" : "=f"(e2_) : "r"(ea_ + cC4));          \
    float ceA_ = __expf(e0_);                                                      \
    float ceB_ = __expf(e1_);                                                      \
    float ceC_ = __expf(e2_);                                                      \
    if ((t & 3) == 0) {                                                            \
        float r0_, r1_;                                                            \
        asm volatile("ld.shared.f32 %0, [%1];" : "=f"(r0_) : "r"(rb_));            \
        asm volatile("ld.shared.f32 %0, [%1];" : "=f"(r1_) : "r"(rb_ + 320));      \
        float ref_ = r0_ + r1_;                                                    \
        float inv_ = __fdividef(1.f, ref_);                                        \
        ceA_ *= inv_; ceB_ *= inv_; ceC_ *= inv_;                                  \
        M_ += (double)__logf(ref_);                                                \
    }                                                                              \
    ull a0_ = 0ull, a1_ = 0ull, b0_ = 0ull, b1_ = 0ull, c0_ = 0ull, c1_ = 0ull;    \
    const unsigned lo_ = rb_ + rb4;                                                \
    const unsigned hi_ = rb_ + 320u + rb4;                                         \
    _Pragma("unroll")                                                              \
    for (int c = 0; c < 3; c++) {                                                  \
        ull P0, P1, P2, P3, Q0, Q1, Q2, Q3;                                        \
        asm volatile("ld.shared.v2.u64 {%0, %1}, [%2];"                            \
            : "=l"(P0), "=l"(P1) : "r"(lo_ + c * 32));                             \
        asm volatile("ld.shared.v2.u64 {%0, %1}, [%2];"                            \
            : "=l"(P2), "=l"(P3) : "r"(lo_ + c * 32 + 16));                        \
        asm volatile("ld.shared.v2.u64 {%0, %1}, [%2];"                            \
            : "=l"(Q0), "=l"(Q1) : "r"(hi_ + c * 32));                             \
        asm volatile("ld.shared.v2.u64 {%0, %1}, [%2];"                            \
            : "=l"(Q2), "=l"(Q3) : "r"(hi_ + c * 32 + 16));                        \
        ull U0 = add2(P0, Q0);                                                     \
        ull U1 = add2(P1, Q1);                                                     \
        ull U2 = add2(P2, Q2);                                                     \
        ull U3 = add2(P3, Q3);                                                     \
        fma2(a0_, U0, EA[4*c  ]); fma2(b0_, U0, EB[4*c  ]); fma2(c0_, U0, EC[4*c  ]); \
        fma2(a1_, U1, EA[4*c+1]); fma2(b1_, U1, EB[4*c+1]); fma2(c1_, U1, EC[4*c+1]); \
        fma2(a0_, U2, EA[4*c+2]); fma2(b0_, U2, EB[4*c+2]); fma2(c0_, U2, EC[4*c+2]); \
        fma2(a1_, U3, EA[4*c+3]); fma2(b1_, U3, EB[4*c+3]); fma2(c1_, U3, EC[4*c+3]); \
    }                                                                              \
    pA_ = hsum2(a0_, a1_) * ceA_;                                                  \
    pB_ = hsum2(b0_, b1_) * ceB_;                                                  \
    pC_ = hsum2(c0_, c1_) * ceC_;                                                  \
    const unsigned st_ = wb_ + stoff;                                              \
    asm volatile("st.shared.f32 [%0], %1;" :: "r"(st_),       "f"(pA_));           \
    asm volatile("st.shared.f32 [%0], %1;" :: "r"(st_ + 64),  "f"(pB_));           \
    asm volatile("st.shared.f32 [%0], %1;" :: "r"(st_ + 128), "f"(pC_));           \
} while (0)

// One warp per block; each warp runs TWO batches (length-sorted pairing:
// perm[k] short + perm[1023-k] long) so total steps per warp ~ const and
// 512 blocks => <=1 warp per SMSP. E = exp(transitions) shared by the pair.
extern "C" __global__ void __launch_bounds__(32)
crf_kernel(const float* __restrict__ em,      // [B,S,T]
           const int*   __restrict__ tags,    // [B,S]
           const float* __restrict__ trans,   // [T,T]
           const float* __restrict__ startt,  // [T]
           const float* __restrict__ endt,    // [T]
           float* __restrict__ out)
{
    const int lane = threadIdx.x;
    const int b0 = g_perm[blockIdx.x];
    const int b1 = g_perm[BB - 1 - blockIdx.x];
    const int len0 = g_len[b0];
    const int len1 = g_len[b1];

    __shared__ __align__(16) float em_s[2][RING][TT];      // 192B row stride
    __shared__ __align__(16) float p_buf[2][2][2][80];     // [batch][parity][half][80]

    const int j     = lane & 15;
    const int half  = lane >> 4;
    const int rbase = half * 24;
    const unsigned cA4 = (unsigned)(j * 4);
    const unsigned cB4 = cA4 + 64u;
    const unsigned cC4 = cA4 + 128u;
    const unsigned rb4 = (unsigned)(rbase * 4);
    const int cA = j, cB = j + 16, cC = j + 32;

    // ---- gold path scores for both batches ----
    float gold0, gold1;
    {
        float g0 = 0.f, g1 = 0.f;
        #pragma unroll 2
        for (int it = 0; it < SS / 32; it++) {
            int t = lane + it * 32;
            if (t < len0) {
                int tg = tags[b0 * SS + t];
                long eb = (long)b0 * SS * TT;
                if (t == 0) g0 += __ldg(&startt[tg]) + __ldg(&em[eb + tg]);
                else {
                    int tp = tags[b0 * SS + t - 1];
                    g0 += __ldg(&trans[tg * TT + tp]) + __ldg(&em[eb + (long)t * TT + tg]);
                }
                if (t == len0 - 1) g0 += __ldg(&endt[tg]);
            }
            if (t < len1) {
                int tg = tags[b1 * SS + t];
                long eb = (long)b1 * SS * TT;
                if (t == 0) g1 += __ldg(&startt[tg]) + __ldg(&em[eb + tg]);
                else {
                    int tp = tags[b1 * SS + t - 1];
                    g1 += __ldg(&trans[tg * TT + tp]) + __ldg(&em[eb + (long)t * TT + tg]);
                }
                if (t == len1 - 1) g1 += __ldg(&endt[tg]);
            }
        }
        gold0 = warp_sum_f(g0);
        gold1 = warp_sum_f(g1);
    }

    // ---- E = exp(transitions): this lane's 24 rows x 3 columns (shared) ----
    ull EA[12], EB[12], EC[12];
    #pragma unroll
    for (int k = 0; k < 12; k++) {
        int r = rbase + 2 * k;
        EA[k] = pack2f(__expf(__ldg(&trans[r * TT + cA])),
                       __expf(__ldg(&trans[(r + 1) * TT + cA])));
        EB[k] = pack2f(__expf(__ldg(&trans[r * TT + cB])),
                       __expf(__ldg(&trans[(r + 1) * TT + cB])));
        EC[k] = pack2f(__expf(__ldg(&trans[r * TT + cC])),
                       __expf(__ldg(&trans[(r + 1) * TT + cC])));
    }

    const float* emp0 = em + (long)b0 * SS * TT;
    const float* emp1 = em + (long)b1 * SS * TT;

    const unsigned ring0b = (unsigned)__cvta_generic_to_shared(&em_s[0][0][0]);
    const unsigned ring1b = (unsigned)__cvta_generic_to_shared(&em_s[1][0][0]);
    const unsigned pbuf0b = (unsigned)__cvta_generic_to_shared(&p_buf[0][0][0][0]);
    const unsigned pbuf1b = (unsigned)__cvta_generic_to_shared(&p_buf[1][0][0][0]);
    const unsigned stoff  = (unsigned)(half * 320 + j * 4);

    // ---- init both batches at t = 0 ----
    float p0A, p0B, p0C, p1A, p1B, p1C;
    double M0, M1;
    {
        float sA = __ldg(&startt[cA]), sB = __ldg(&startt[cB]), sC = __ldg(&startt[cC]);
        float a0 = sA + emp0[cA], b0v = sB + emp0[cB], c0v = sC + emp0[cC];
        float a1 = sA + emp1[cA], b1v = sB + emp1[cB], c1v = sC + emp1[cC];
        float r0 = __shfl_sync(FULL, a0, 0);
        float r1 = __shfl_sync(FULL, a1, 0);
        M0 = (double)r0; M1 = (double)r1;
        p0A = (half == 0) ? __expf(a0 - r0) : 0.f;
        p0B = (half == 0) ? __expf(b0v - r0) : 0.f;
        p0C = (half == 0) ? __expf(c0v - r0) : 0.f;
        p1A = (half == 0) ? __expf(a1 - r1) : 0.f;
        p1B = (half == 0) ? __expf(b1v - r1) : 0.f;
        p1C = (half == 0) ? __expf(c1v - r1) : 0.f;
        unsigned s0 = pbuf0b + stoff, s1 = pbuf1b + stoff;
        asm volatile("st.shared.f32 [%0], %1;" :: "r"(s0),       "f"(p0A));
        asm volatile("st.shared.f32 [%0], %1;" :: "r"(s0 + 64),  "f"(p0B));
        asm volatile("st.shared.f32 [%0], %1;" :: "r"(s0 + 128), "f"(p0C));
        asm volatile("st.shared.f32 [%0], %1;" :: "r"(s1),       "f"(p1A));
        asm volatile("st.shared.f32 [%0], %1;" :: "r"(s1 + 64),  "f"(p1B));
        asm volatile("st.shared.f32 [%0], %1;" :: "r"(s1 + 128), "f"(p1C));
    }

    // per-lane prefetch assignment: lanes 0-11 -> batch0, 12-23 -> batch1
    const int quad = (lane < 12) ? lane : (lane - 12);
    const unsigned pf_dstA = ((lane < 12) ? ring0b : ring1b) + (unsigned)(quad * 16);
    const float*   pf_srcA = ((lane < 12) ? emp0 : emp1) + quad * 4;
    const int      lenqA   = (lane < 12) ? len0 : ((lane < 24) ? len1 : 0);

    // ---- prologue: rows 1..LEAD for both batches ----
    #pragma unroll
    for (int s = 1; s <= LEAD; s++) {
        cp_async16_pred(pf_dstA + (unsigned)((s & (RING - 1)) * 192),
                        pf_srcA + (long)s * TT, s < lenqA);
        asm volatile("cp.async.commit_group;");
    }

    const int tmin = (len0 < len1) ? len0 : len1;
    const int tmax = (len0 < len1) ? len1 : len0;

    // ---- phase A: both batches ----
    #pragma unroll 1
    for (int t = 1; t < tmin; t++) {
        int s = t + LEAD;
        cp_async16_pred(pf_dstA + (unsigned)((s & (RING - 1)) * 192),
                        pf_srcA + (long)s * TT, s < lenqA);
        asm volatile("cp.async.commit_group;");
        asm volatile("cp.async.wait_group 14;" ::: "memory");
        STEP_BODY(p0A, p0B, p0C, M0, ring0b, pbuf0b);
        STEP_BODY(p1A, p1B, p1C, M1, ring1b, pbuf1b);
    }

    // ---- phase B: longer batch only (uniform select, no copies of E) ----
    const bool use1 = (len1 > len0);
    float qA = use1 ? p1A : p0A;
    float qB = use1 ? p1B : p0B;
    float qC = use1 ? p1C : p0C;
    double Mq = use1 ? M1 : M0;
    const unsigned ringSb = use1 ? ring1b : ring0b;
    const unsigned pbufSb = use1 ? pbuf1b : pbuf0b;
    const float*   pf_srcB = (use1 ? emp1 : emp0) + quad * 4;
    const unsigned pf_dstB = ringSb + (unsigned)(quad * 16);
    const int      lenqB   = (lane < 12) ? tmax : 0;

    #pragma unroll 1
    for (int t = tmin; t < tmax; t++) {
        int s = t + LEAD;
        cp_async16_pred(pf_dstB + (unsigned)((s & (RING - 1)) * 192),
                        pf_srcB + (long)s * TT, s < lenqB);
        asm volatile("cp.async.commit_group;");
        asm volatile("cp.async.wait_group 14;" ::: "memory");
        STEP_BODY(qA, qB, qC, Mq, ringSb, pbufSb);
    }
    asm volatile("cp.async.wait_group 0;" ::: "memory");

    // ---- finals ----
    const float eeA = __expf(__ldg(&endt[cA]));
    const float eeB = __expf(__ldg(&endt[cB]));
    const float eeC = __expf(__ldg(&endt[cC]));

    // shorter batch: its state froze at the end of phase A
    {
        float shA = use1 ? p0A : p1A;
        float shB = use1 ? p0B : p1B;
        float shC = use1 ? p0C : p1C;
        double Ms = use1 ? M0 : M1;
        int   bsh = use1 ? b0 : b1;
        float gsh = use1 ? gold0 : gold1;
        float v = shA * eeA + shB * eeB + shC * eeC;
        float ssum = warp_sum_f(v);
        if (lane == 0)
            g_scratch[bsh] = Ms + (double)__logf(ssum) - (double)gsh;
    }
    // longer batch
    {
        double Ml = Mq;
        int   blg = use1 ? b1 : b0;
        float glg = use1 ? gold1 : gold0;
        float v = qA * eeA + qB * eeB + qC * eeC;
        float ssum = warp_sum_f(v);
        if (lane == 0)
            g_scratch[blg] = Ml + (double)__logf(ssum) - (double)glg;
    }

    // ---- fused mean: last block reduces ----
    unsigned r = 0;
    if (lane == 0) {
        __threadfence();
        r = atomicAdd(&g_count, 1u);
    }
    r = __shfl_sync(FULL, r, 0);
    if (r == gridDim.x - 1) {
        __threadfence();
        double s = 0.0;
        for (int i = lane; i < BB; i += 32) s += g_scratch[i];
        #pragma unroll
        for (int o = 16; o; o >>= 1) s += __shfl_xor_sync(FULL, s, o);
        if (lane == 0) {
            out[0] = (float)(s / (double)BB);
            g_count = 0;   // reset for next graph replay
        }
    }
}

extern "C" void kernel_launch(void* const* d_in, const int* in_sizes, int n_in,
                              void* d_out, int out_size) {
    const float* em     = (const float*)d_in[0];
    const int*   tags   = (const int*)d_in[1];
    const float* mask   = (const float*)d_in[2];
    const float* trans  = (const float*)d_in[3];
    const float* startt = (const float*)d_in[4];
    const float* endt   = (const float*)d_in[5];
    float* out = (float*)d_out;

    len_kernel<<<BB / 4, 128>>>(mask);
    sort_kernel<<<1, 512>>>();
    crf_kernel<<<BB / 2, 32>>>(em, tags, trans, startt, endt, out);
}

// round 7
// speedup vs baseline: 1.2492x; 1.2492x over previous
#include <cuda_runtime.h>
#include <cuda_bf16.h>
#include <cstdint>

#define BB 1024
#define SS 512
#define TT 48
#define FULL 0xFFFFFFFFu
#define RING 16
#define LEAD (RING - 2)   // 14 steps of prefetch lead

typedef unsigned long long ull;

__device__ double g_scratch[BB];
__device__ unsigned int g_count = 0;
__device__ int g_len[BB];
__device__ int g_perm[BB];

__device__ __forceinline__ ull pack2f(float a, float b) {
    ull r;
    asm("mov.b64 %0, {%1, %2};" : "=l"(r) : "f"(a), "f"(b));
    return r;
}
__device__ __forceinline__ void unpack2f(ull v, float& lo, float& hi) {
    asm("mov.b64 {%0, %1}, %2;" : "=f"(lo), "=f"(hi) : "l"(v));
}
__device__ __forceinline__ void fma2(ull& acc, ull a, ull b) {
    asm("fma.rn.f32x2 %0, %1, %2, %0;" : "+l"(acc) : "l"(a), "l"(b));
}
__device__ __forceinline__ ull add2(ull a, ull b) {
    ull r;
    asm("add.rn.f32x2 %0, %1, %2;" : "=l"(r) : "l"(a), "l"(b));
    return r;
}
__device__ __forceinline__ float hsum2(ull a, ull b) {
    ull u = add2(a, b);
    float lo, hi;
    unpack2f(u, lo, hi);
    return lo + hi;
}
__device__ __forceinline__ float warp_sum_f(float v) {
    #pragma unroll
    for (int o = 16; o; o >>= 1) v += __shfl_xor_sync(FULL, v, o);
    return v;
}
// Predicated cp.async: no BSSY/BSYNC divergence cost.
__device__ __forceinline__ void cp_async16_pred(unsigned dst, const float* src, int go) {
    asm volatile(
        "{\n\t.reg .pred p;\n\t"
        "setp.ne.b32 p, %0, 0;\n\t"
        "@p cp.async.cg.shared.global [%1], [%2], 16;\n\t}"
        :: "r"(go), "r"(dst), "l"(src));
}

// ---------- pre-pass 1: sequence lengths ----------
extern "C" __global__ void __launch_bounds__(128)
len_kernel(const float* __restrict__ mask) {
    const int lane = threadIdx.x & 31;
    const int b = blockIdx.x * 4 + (threadIdx.x >> 5);
    float s = 0.f;
    #pragma unroll
    for (int k = 0; k < SS / 32; k++) s += mask[b * SS + k * 32 + lane];
    s = warp_sum_f(s);
    if (lane == 0) g_len[b] = __float2int_rn(s);
}

// ---------- pre-pass 2: counting sort of batches by length ----------
extern "C" __global__ void __launch_bounds__(512)
sort_kernel() {
    __shared__ int hist[SS + 1];
    const int tid = threadIdx.x;
    for (int i = tid; i <= SS; i += 512) hist[i] = 0;
    __syncthreads();
    for (int b = tid; b < BB; b += 512) atomicAdd(&hist[g_len[b]], 1);
    __syncthreads();
    if (tid == 0) {
        int acc = 0;
        for (int i = 0; i <= SS; i++) { int c = hist[i]; hist[i] = acc; acc += c; }
    }
    __syncthreads();
    for (int b = tid; b < BB; b += 512) {
        int r = atomicAdd(&hist[g_len[b]], 1);
        g_perm[r] = b;
    }
}

// One step of the product-domain recurrence for one batch.
// Reads partials from parity (t-1)&1 of pbufb_, writes parity t&1.
#define STEP_BODY(pA_, pB_, pC_, M_, ringb_, pbufb_) do {                          \
    const unsigned rb_ = (pbufb_) + (unsigned)(((t - 1) & 1) * 640);               \
    const unsigned wb_ = (pbufb_) + (unsigned)((t & 1) * 640);                     \
    const unsigned ea_ = (ringb_) + (unsigned)((t & (RING - 1)) * 192);            \
    float e0_, e1_, e2_;                                                           \
    asm volatile("ld.shared.f32 %0, [%1];" : "=f"(e0_) : "r"(ea_ + cA4));          \
    asm volatile("ld.shared.f32 %0, [%1];" : "=f"(e1_) : "r"(ea_ + cB4));          \
    asm volatile("ld.shared.f32 %0, [%1];" : "=f"(e2_) : "r"(ea_ + cC4));          \
    float ceA_ = __expf(e0_);                                                      \
    float ceB_ = __expf(e1_);                                                      \
    float ceC_ = __expf(e2_);                                                      \
    if ((t & 3) == 0) {                                                            \
        float r0_, r1_;                                                            \
        asm volatile("ld.shared.f32 %0, [%1];" : "=f"(r0_) : "r"(rb_));            \
        asm volatile("ld.shared.f32 %0, [%1];" : "=f"(r1_) : "r"(rb_ + 320));      \
        float ref_ = r0_ + r1_;                                                    \
        float inv_ = __fdividef(1.f, ref_);                                        \
        ceA_ *= inv_; ceB_ *= inv_; ceC_ *= inv_;                                  \
        M_ += (double)__logf(ref_);                                                \
    }                                                                              \
    ull a0_ = 0ull, a1_ = 0ull, b0_ = 0ull, b1_ = 0ull, c0_ = 0ull, c1_ = 0ull;    \
    const unsigned lo_ = rb_ + rb4;                                                \
    const unsigned hi_ = rb_ + 320u + rb4;                                         \
    _Pragma("unroll")                                                              \
    for (int c = 0; c < 3; c++) {                                                  \
        ull P0, P1, P2, P3, Q0, Q1, Q2, Q3;                                        \
        asm volatile("ld.shared.v2.u64 {%0, %1}, [%2];"                            \
            : "=l"(P0), "=l"(P1) : "r"(lo_ + c * 32));                             \
        asm volatile("ld.shared.v2.u64 {%0, %1}, [%2];"                            \
            : "=l"(P2), "=l"(P3) : "r"(lo_ + c * 32 + 16));                        \
        asm volatile("ld.shared.v2.u64 {%0, %1}, [%2];"                            \
            : "=l"(Q0), "=l"(Q1) : "r"(hi_ + c * 32));                             \
        asm volatile("ld.shared.v2.u64 {%0, %1}, [%2];"                            \
            : "=l"(Q2), "=l"(Q3) : "r"(hi_ + c * 32 + 16));                        \
        ull U0 = add2(P0, Q0);                                                     \
        ull U1 = add2(P1, Q1);                                                     \
        ull U2 = add2(P2, Q2);                                                     \
        ull U3 = add2(P3, Q3);                                                     \
        fma2(a0_, U0, EA[4*c  ]); fma2(b0_, U0, EB[4*c  ]); fma2(c0_, U0, EC[4*c  ]); \
        fma2(a1_, U1, EA[4*c+1]); fma2(b1_, U1, EB[4*c+1]); fma2(c1_, U1, EC[4*c+1]); \
        fma2(a0_, U2, EA[4*c+2]); fma2(b0_, U2, EB[4*c+2]); fma2(c0_, U2, EC[4*c+2]); \
        fma2(a1_, U3, EA[4*c+3]); fma2(b1_, U3, EB[4*c+3]); fma2(c1_, U3, EC[4*c+3]); \
    }                                                                              \
    pA_ = hsum2(a0_, a1_) * ceA_;                                                  \
    pB_ = hsum2(b0_, b1_) * ceB_;                                                  \
    pC_ = hsum2(c0_, c1_) * ceC_;                                                  \
    const unsigned st_ = wb_ + stoff;                                              \
    asm volatile("st.shared.f32 [%0], %1;" :: "r"(st_),       "f"(pA_));           \
    asm volatile("st.shared.f32 [%0], %1;" :: "r"(st_ + 64),  "f"(pB_));           \
    asm volatile("st.shared.f32 [%0], %1;" :: "r"(st_ + 128), "f"(pC_));           \
} while (0)

// 128-thread blocks (4 warps -> wid%4 spreads one warp per SMSP). Each warp
// independently runs a length-sorted batch pair (perm[k] + perm[1023-k]) in
// its own smem slice: total steps per warp ~ const, every SMSP filled.
extern "C" __global__ void __launch_bounds__(128)
crf_kernel(const float* __restrict__ em,      // [B,S,T]
           const int*   __restrict__ tags,    // [B,S]
           const float* __restrict__ trans,   // [T,T]
           const float* __restrict__ startt,  // [T]
           const float* __restrict__ endt,    // [T]
           float* __restrict__ out)
{
    const int lane = threadIdx.x & 31;
    const int wid  = threadIdx.x >> 5;
    const int pairIdx = blockIdx.x * 4 + wid;       // 0..511
    const int b0 = g_perm[pairIdx];
    const int b1 = g_perm[BB - 1 - pairIdx];
    const int len0 = g_len[b0];
    const int len1 = g_len[b1];

    __shared__ __align__(16) float em_s[4][2][RING][TT];      // per-warp rings
    __shared__ __align__(16) float p_buf[4][2][2][2][80];     // [warp][batch][parity][half][80]

    const int j     = lane & 15;
    const int half  = lane >> 4;
    const int rbase = half * 24;
    const unsigned cA4 = (unsigned)(j * 4);
    const unsigned cB4 = cA4 + 64u;
    const unsigned cC4 = cA4 + 128u;
    const unsigned rb4 = (unsigned)(rbase * 4);
    const int cA = j, cB = j + 16, cC = j + 32;

    // ---- gold path scores for both batches ----
    float gold0, gold1;
    {
        float g0 = 0.f, g1 = 0.f;
        #pragma unroll 2
        for (int it = 0; it < SS / 32; it++) {
            int t = lane + it * 32;
            if (t < len0) {
                int tg = tags[b0 * SS + t];
                long eb = (long)b0 * SS * TT;
                if (t == 0) g0 += __ldg(&startt[tg]) + __ldg(&em[eb + tg]);
                else {
                    int tp = tags[b0 * SS + t - 1];
                    g0 += __ldg(&trans[tg * TT + tp]) + __ldg(&em[eb + (long)t * TT + tg]);
                }
                if (t == len0 - 1) g0 += __ldg(&endt[tg]);
            }
            if (t < len1) {
                int tg = tags[b1 * SS + t];
                long eb = (long)b1 * SS * TT;
                if (t == 0) g1 += __ldg(&startt[tg]) + __ldg(&em[eb + tg]);
                else {
                    int tp = tags[b1 * SS + t - 1];
                    g1 += __ldg(&trans[tg * TT + tp]) + __ldg(&em[eb + (long)t * TT + tg]);
                }
                if (t == len1 - 1) g1 += __ldg(&endt[tg]);
            }
        }
        gold0 = warp_sum_f(g0);
        gold1 = warp_sum_f(g1);
    }

    // ---- E = exp(transitions): this lane's 24 rows x 3 columns (shared) ----
    ull EA[12], EB[12], EC[12];
    #pragma unroll
    for (int k = 0; k < 12; k++) {
        int r = rbase + 2 * k;
        EA[k] = pack2f(__expf(__ldg(&trans[r * TT + cA])),
                       __expf(__ldg(&trans[(r + 1) * TT + cA])));
        EB[k] = pack2f(__expf(__ldg(&trans[r * TT + cB])),
                       __expf(__ldg(&trans[(r + 1) * TT + cB])));
        EC[k] = pack2f(__expf(__ldg(&trans[r * TT + cC])),
                       __expf(__ldg(&trans[(r + 1) * TT + cC])));
    }

    const float* emp0 = em + (long)b0 * SS * TT;
    const float* emp1 = em + (long)b1 * SS * TT;

    const unsigned ring0b = (unsigned)__cvta_generic_to_shared(&em_s[wid][0][0][0]);
    const unsigned ring1b = (unsigned)__cvta_generic_to_shared(&em_s[wid][1][0][0]);
    const unsigned pbuf0b = (unsigned)__cvta_generic_to_shared(&p_buf[wid][0][0][0][0]);
    const unsigned pbuf1b = (unsigned)__cvta_generic_to_shared(&p_buf[wid][1][0][0][0]);
    const unsigned stoff  = (unsigned)(half * 320 + j * 4);

    // ---- init both batches at t = 0 ----
    float p0A, p0B, p0C, p1A, p1B, p1C;
    double M0, M1;
    {
        float sA = __ldg(&startt[cA]), sB = __ldg(&startt[cB]), sC = __ldg(&startt[cC]);
        float a0 = sA + emp0[cA], b0v = sB + emp0[cB], c0v = sC + emp0[cC];
        float a1 = sA + emp1[cA], b1v = sB + emp1[cB], c1v = sC + emp1[cC];
        float r0 = __shfl_sync(FULL, a0, 0);
        float r1 = __shfl_sync(FULL, a1, 0);
        M0 = (double)r0; M1 = (double)r1;
        p0A = (half == 0) ? __expf(a0 - r0) : 0.f;
        p0B = (half == 0) ? __expf(b0v - r0) : 0.f;
        p0C = (half == 0) ? __expf(c0v - r0) : 0.f;
        p1A = (half == 0) ? __expf(a1 - r1) : 0.f;
        p1B = (half == 0) ? __expf(b1v - r1) : 0.f;
        p1C = (half == 0) ? __expf(c1v - r1) : 0.f;
        unsigned s0 = pbuf0b + stoff, s1 = pbuf1b + stoff;
        asm volatile("st.shared.f32 [%0], %1;" :: "r"(s0),       "f"(p0A));
        asm volatile("st.shared.f32 [%0], %1;" :: "r"(s0 + 64),  "f"(p0B));
        asm volatile("st.shared.f32 [%0], %1;" :: "r"(s0 + 128), "f"(p0C));
        asm volatile("st.shared.f32 [%0], %1;" :: "r"(s1),       "f"(p1A));
        asm volatile("st.shared.f32 [%0], %1;" :: "r"(s1 + 64),  "f"(p1B));
        asm volatile("st.shared.f32 [%0], %1;" :: "r"(s1 + 128), "f"(p1C));
    }

    // per-lane prefetch assignment: lanes 0-11 -> batch0, 12-23 -> batch1
    const int quad = (lane < 12) ? lane : (lane - 12);
    const unsigned pf_dstA = ((lane < 12) ? ring0b : ring1b) + (unsigned)(quad * 16);
    const float*   pf_srcA = ((lane < 12) ? emp0 : emp1) + quad * 4;
    const int      lenqA   = (lane < 12) ? len0 : ((lane < 24) ? len1 : 0);

    // ---- prologue: rows 1..LEAD for both batches ----
    #pragma unroll
    for (int s = 1; s <= LEAD; s++) {
        cp_async16_pred(pf_dstA + (unsigned)((s & (RING - 1)) * 192),
                        pf_srcA + (long)s * TT, s < lenqA);
        asm volatile("cp.async.commit_group;");
    }

    const int tmin = (len0 < len1) ? len0 : len1;
    const int tmax = (len0 < len1) ? len1 : len0;

    // ---- phase A: both batches ----
    #pragma unroll 1
    for (int t = 1; t < tmin; t++) {
        int s = t + LEAD;
        cp_async16_pred(pf_dstA + (unsigned)((s & (RING - 1)) * 192),
                        pf_srcA + (long)s * TT, s < lenqA);
        asm volatile("cp.async.commit_group;");
        asm volatile("cp.async.wait_group 14;" ::: "memory");
        STEP_BODY(p0A, p0B, p0C, M0, ring0b, pbuf0b);
        STEP_BODY(p1A, p1B, p1C, M1, ring1b, pbuf1b);
    }

    // ---- phase B: longer batch only (uniform select) ----
    const bool use1 = (len1 > len0);
    float qA = use1 ? p1A : p0A;
    float qB = use1 ? p1B : p0B;
    float qC = use1 ? p1C : p0C;
    double Mq = use1 ? M1 : M0;
    const unsigned ringSb = use1 ? ring1b : ring0b;
    const unsigned pbufSb = use1 ? pbuf1b : pbuf0b;
    const float*   pf_srcB = (use1 ? emp1 : emp0) + quad * 4;
    const unsigned pf_dstB = ringSb + (unsigned)(quad * 16);
    const int      lenqB   = (lane < 12) ? tmax : 0;

    #pragma unroll 1
    for (int t = tmin; t < tmax; t++) {
        int s = t + LEAD;
        cp_async16_pred(pf_dstB + (unsigned)((s & (RING - 1)) * 192),
                        pf_srcB + (long)s * TT, s < lenqB);
        asm volatile("cp.async.commit_group;");
        asm volatile("cp.async.wait_group 14;" ::: "memory");
        STEP_BODY(qA, qB, qC, Mq, ringSb, pbufSb);
    }
    asm volatile("cp.async.wait_group 0;" ::: "memory");

    // ---- finals ----
    const float eeA = __expf(__ldg(&endt[cA]));
    const float eeB = __expf(__ldg(&endt[cB]));
    const float eeC = __expf(__ldg(&endt[cC]));

    // shorter batch: its state froze at the end of phase A
    {
        float shA = use1 ? p0A : p1A;
        float shB = use1 ? p0B : p1B;
        float shC = use1 ? p0C : p1C;
        double Ms = use1 ? M0 : M1;
        int   bsh = use1 ? b0 : b1;
        float gsh = use1 ? gold0 : gold1;
        float v = shA * eeA + shB * eeB + shC * eeC;
        float ssum = warp_sum_f(v);
        if (lane == 0)
            g_scratch[bsh] = Ms + (double)__logf(ssum) - (double)gsh;
    }
    // longer batch
    {
        int   blg = use1 ? b1 : b0;
        float glg = use1 ? gold1 : gold0;
        float v = qA * eeA + qB * eeB + qC * eeC;
        float ssum = warp_sum_f(v);
        if (lane == 0)
            g_scratch[blg] = Mq + (double)__logf(ssum) - (double)glg;
    }

    // ---- fused mean: last block reduces (block-level handshake) ----
    __syncthreads();
    __shared__ bool is_last;
    if (threadIdx.x == 0) {
        __threadfence();
        unsigned r = atomicAdd(&g_count, 1u);
        is_last = (r == gridDim.x - 1);
    }
    __syncthreads();
    if (is_last) {
        __threadfence();
        double s = 0.0;
        for (int i = threadIdx.x; i < BB; i += 128) s += g_scratch[i];
        __shared__ double sh[128];
        sh[threadIdx.x] = s;
        __syncthreads();
        #pragma unroll
        for (int o = 64; o; o >>= 1) {
            if (threadIdx.x < o) sh[threadIdx.x] += sh[threadIdx.x + o];
            __syncthreads();
        }
        if (threadIdx.x == 0) {
            out[0] = (float)(sh[0] / (double)BB);
            g_count = 0;   // reset for next graph replay
        }
    }
}

extern "C" void kernel_launch(void* const* d_in, const int* in_sizes, int n_in,
                              void* d_out, int out_size) {
    const float* em     = (const float*)d_in[0];
    const int*   tags   = (const int*)d_in[1];
    const float* mask   = (const float*)d_in[2];
    const float* trans  = (const float*)d_in[3];
    const float* startt = (const float*)d_in[4];
    const float* endt   = (const float*)d_in[5];
    float* out = (float*)d_out;

    len_kernel<<<BB / 4, 128>>>(mask);
    sort_kernel<<<1, 512>>>();
    crf_kernel<<<BB / 8, 128>>>(em, tags, trans, startt, endt, out);
}